// round 11
// baseline (speedup 1.0000x reference)
#include <cuda_runtime.h>
#include <cuda_fp16.h>
#include <math.h>
#include <stdint.h>

#define DIMM 1024
#define NHEAD 16
#define HDIM 64
#define SLEN 2048
#define BSZ 2
#define NTOK (BSZ*SLEN)          // 4096
#define NEXP 8
#define TOPK 2
#define HIDD 1024
#define NSLOT (NTOK*TOPK)        // 8192
#define EPSV 1e-6f

// GEMM pipeline constants (BK=64, 3 stages)
#define AST 72                   // A row stride (halves)
#define BST 136                  // B row stride (halves)
#define A_STAGE (128*AST)        // 9216 halves
#define B_STAGE (64*BST)         // 8704 halves
#define STAGES 3
#define SMEMB (STAGES*(A_STAGE+B_STAGE)*2)   // 107520 B

// ================= scratch =================
__device__ __half g_wqkvh[(size_t)3*DIMM*DIMM];
__device__ __half g_woh[(size_t)DIMM*DIMM];
__device__ __half g_e13h[(size_t)2*NEXP*DIMM*HIDD];
__device__ __half g_e2h[(size_t)NEXP*HIDD*DIMM];
__device__ __half g_s13wh[(size_t)2*DIMM*HIDD];
__device__ __half g_s2wh[(size_t)HIDD*DIMM];
__device__ __half g_xnh[(size_t)NTOK*DIMM];
__device__ __half g_qkvh[(size_t)3*NTOK*DIMM];
__device__ __half g_atth[(size_t)NTOK*DIMM];
__device__ __half g_hnh[(size_t)NTOK*DIMM];
__device__ __half g_h13h[(size_t)2*NSLOT*HIDD];
__device__ __half g_g13h[(size_t)NSLOT*HIDD];
__device__ __half g_s13hh[(size_t)2*NTOK*HIDD];
__device__ __half g_s13h[(size_t)NTOK*HIDD];
__device__ __half g_eoh[(size_t)NSLOT*DIMM];
__device__ float g_h[(size_t)NTOK*DIMM];
__device__ float g_hn32[(size_t)NTOK*DIMM];
__device__ int   g_topk_idx[NTOK*TOPK];
__device__ float g_topk_w [NTOK*TOPK];
__device__ int   g_counts[NEXP];
__device__ int   g_offsets[NEXP+1];
__device__ int   g_fill[NEXP];
__device__ int   g_tok_idx[NSLOT];
__device__ int   g_slot_map[NTOK*TOPK];

__device__ __forceinline__ uint32_t f2h2(float lo, float hi) {
    __half2 h = __floats2half2_rn(lo, hi);
    return *reinterpret_cast<uint32_t*>(&h);
}
__device__ __forceinline__ uint32_t smem_u32(const void* p) {
    uint32_t a;
    asm("{ .reg .u64 t; cvta.to.shared.u64 t, %1; cvt.u32.u64 %0, t; }" : "=r"(a) : "l"(p));
    return a;
}

#define MMA16816(acc, a0,a1,a2,a3, b0,b1) \
    asm volatile( \
        "mma.sync.aligned.m16n8k16.row.col.f32.f16.f16.f32 " \
        "{%0,%1,%2,%3}, {%4,%5,%6,%7}, {%8,%9}, {%0,%1,%2,%3};" \
        : "+f"((acc)[0]), "+f"((acc)[1]), "+f"((acc)[2]), "+f"((acc)[3]) \
        : "r"(a0), "r"(a1), "r"(a2), "r"(a3), "r"(b0), "r"(b1))

#define LDSM_X4(r, addr) \
    asm volatile("ldmatrix.sync.aligned.m8n8.x4.shared.b16 {%0,%1,%2,%3}, [%4];" \
        : "=r"((r)[0]),"=r"((r)[1]),"=r"((r)[2]),"=r"((r)[3]) : "r"(addr))
#define LDSM_X4T(r, addr) \
    asm volatile("ldmatrix.sync.aligned.m8n8.x4.trans.shared.b16 {%0,%1,%2,%3}, [%4];" \
        : "=r"((r)[0]),"=r"((r)[1]),"=r"((r)[2]),"=r"((r)[3]) : "r"(addr))

#define CP16(dst, src, sz) \
    asm volatile("cp.async.cg.shared.global [%0], [%1], 16, %2;" \
        :: "r"(dst), "l"(src), "r"(sz) : "memory")
#define CPCOMMIT asm volatile("cp.async.commit_group;" ::: "memory")
#define CPWAIT1  asm volatile("cp.async.wait_group 1;" ::: "memory")
#define CPWAIT0  asm volatile("cp.async.wait_group 0;" ::: "memory")

// ================= GEMM: half A [M,1024], half B [1024,1024] =================
// BK=64 chunks, 3-stage cp.async pipeline, 16 mainloop iterations.
template<bool GATHER, bool GROUPED, bool RESID, bool HALFOUT, bool ROPE, bool COMBINE>
__global__ void __launch_bounds__(256) gemm2(
    const __half* __restrict__ A, const __half* __restrict__ B,
    void* __restrict__ Cv, const float* __restrict__ Rr,
    int M, float scale,
    long long sAo, long long sBo, long long sCo, long long sCg,
    const int* __restrict__ gidx, const int* __restrict__ offsets,
    const float* __restrict__ Fq, const __half* __restrict__ Eo,
    const int* __restrict__ smap, const float* __restrict__ tw)
{
    extern __shared__ __half smx[];
    const int LDA = 1024;
    int tid = threadIdx.x, lane = tid & 31, wid = tid >> 5;
    int warpM = wid & 3, warpN = wid >> 2;
    int z = blockIdx.z;

    float* Cf = (float*)Cv;
    __half* Ch = (__half*)Cv;

    int Mz = M, seg0 = 0;
    if (GROUPED) {
        int e = z & 7;
        seg0 = offsets[e]; Mz = offsets[e+1] - seg0;
        B  += (size_t)z * sBo;
        if (HALFOUT) Ch += (size_t)(z >> 3) * sCg;
        else         Cf += (size_t)(z >> 3) * sCg;
    } else {
        A += (size_t)z * sAo;
        B += (size_t)z * sBo;
        if (HALFOUT) Ch += (size_t)z * sCo; else Cf += (size_t)z * sCo;
        if (RESID) Rr += (size_t)z * sCo;
    }
    int m0 = blockIdx.x * 128;
    if (GROUPED && m0 >= Mz) return;
    int n0 = blockIdx.y * 128;

    uint32_t AsB = smem_u32(smx);
    uint32_t BsB = AsB + STAGES*A_STAGE*2;

    // A loader: 2 threads/row, 4 cp16 each covering 64 halves
    int arow = tid >> 1, acH = (tid & 1)*32;
    bool aOK = (!GROUPED) || ((m0 + arow) < Mz);
    long long grow = 0;
    if (aOK) grow = GATHER ? (long long)gidx[seg0 + m0 + arow]
                  : (GROUPED ? (long long)(seg0 + m0 + arow) : (long long)(m0 + arow));
    const __half* aP = A + (size_t)grow*LDA + acH;
    uint32_t aD = AsB + (arow*AST + acH)*2;
    int aSz = aOK ? 16 : 0;

    // B loader: 4 threads/row (k-rows 0..63), 4 cp16 each covering 128 cols
    int brow = tid >> 2, bH = (tid & 3)*32;
    const __half* bP = B + (size_t)brow*LDA + n0 + bH;
    uint32_t bD = BsB + (brow*BST + bH)*2;

#define LOADST(s_, c_) do { \
    int kt_ = (c_)*64; \
    CP16(aD + (s_)*(A_STAGE*2),      aP + kt_,      aSz); \
    CP16(aD + (s_)*(A_STAGE*2) + 16, aP + kt_ + 8,  aSz); \
    CP16(aD + (s_)*(A_STAGE*2) + 32, aP + kt_ + 16, aSz); \
    CP16(aD + (s_)*(A_STAGE*2) + 48, aP + kt_ + 24, aSz); \
    CP16(bD + (s_)*(B_STAGE*2),      bP + (size_t)kt_*LDA,      16); \
    CP16(bD + (s_)*(B_STAGE*2) + 16, bP + (size_t)kt_*LDA + 8,  16); \
    CP16(bD + (s_)*(B_STAGE*2) + 32, bP + (size_t)kt_*LDA + 16, 16); \
    CP16(bD + (s_)*(B_STAGE*2) + 48, bP + (size_t)kt_*LDA + 24, 16); \
} while (0)

    float acc[2][8][4];
#pragma unroll
    for (int mt = 0; mt < 2; mt++)
#pragma unroll
        for (int nt = 0; nt < 8; nt++)
#pragma unroll
            for (int j = 0; j < 4; j++) acc[mt][nt][j] = 0.f;

    uint32_t aAddr = AsB + ((warpM*32 + (lane & 15))*AST + ((lane >> 4) & 1)*8)*2;
    uint32_t bAddr = BsB + ((lane & 15)*BST + warpN*64 + ((lane >> 4) & 1)*8)*2;

    LOADST(0, 0); CPCOMMIT;
    LOADST(1, 1); CPCOMMIT;

    for (int c = 0; c < 16; c++) {
        CPWAIT1;
        __syncthreads();
        if (c + 2 < 16) { int c2 = c + 2; LOADST(c2 % 3, c2); }
        CPCOMMIT;
        int st = c % 3;
        uint32_t aS = aAddr + st*(A_STAGE*2);
        uint32_t bS = bAddr + st*(B_STAGE*2);
#pragma unroll
        for (int ks = 0; ks < 4; ks++) {
            uint32_t af0[4], af1[4];
            LDSM_X4(af0, aS + ks*32);
            LDSM_X4(af1, aS + ks*32 + 16*AST*2);
            uint32_t bf[4][4];
#pragma unroll
            for (int nt2 = 0; nt2 < 4; nt2++)
                LDSM_X4T(bf[nt2], bS + ks*(16*BST*2) + nt2*32);
#pragma unroll
            for (int nt2 = 0; nt2 < 4; nt2++) {
                MMA16816(acc[0][2*nt2  ], af0[0],af0[1],af0[2],af0[3], bf[nt2][0],bf[nt2][1]);
                MMA16816(acc[0][2*nt2+1], af0[0],af0[1],af0[2],af0[3], bf[nt2][2],bf[nt2][3]);
                MMA16816(acc[1][2*nt2  ], af1[0],af1[1],af1[2],af1[3], bf[nt2][0],bf[nt2][1]);
                MMA16816(acc[1][2*nt2+1], af1[0],af1[1],af1[2],af1[3], bf[nt2][2],bf[nt2][3]);
            }
        }
    }

#pragma unroll
    for (int mt = 0; mt < 2; mt++) {
        int rb = m0 + warpM*32 + mt*16 + (lane >> 2);
#pragma unroll
        for (int hh = 0; hh < 2; hh++) {
            int r = rb + hh*8;
            if (GROUPED && r >= Mz) continue;
            size_t crow = (size_t)((GROUPED ? seg0 : 0) + r) * 1024;
            int cs0 = 0, cs1 = 0; float cw0 = 0.f, cw1 = 0.f;
            if (COMBINE) {
                cs0 = smap[r*2]; cs1 = smap[r*2+1];
                cw0 = tw[r*2];   cw1 = tw[r*2+1];
            }
#pragma unroll
            for (int nt = 0; nt < 8; nt++) {
                int col = n0 + warpN*64 + nt*8 + (lane & 3)*2;
                float vx = acc[mt][nt][hh*2+0]*scale;
                float vy = acc[mt][nt][hh*2+1]*scale;
                if (ROPE) {
                    if (z < 2) {
                        int s = r & (SLEN-1);
                        int p = (col & 63) >> 1;
                        float cc = Fq[(s*(HDIM/2) + p)*2 + 0];
                        float sn = Fq[(s*(HDIM/2) + p)*2 + 1];
                        float rx = vx*cc - vy*sn;
                        float ry = vx*sn + vy*cc;
                        vx = rx; vy = ry;
                    }
                }
                if (HALFOUT) {
                    *(uint32_t*)(Ch + crow + col) = f2h2(vx, vy);
                } else {
                    if (RESID) {
                        float2 rv = *(const float2*)(Rr + crow + col);
                        vx += rv.x; vy += rv.y;
                    }
                    if (COMBINE) {
                        float2 e0 = __half22float2(*(const __half2*)(Eo + (size_t)cs0*1024 + col));
                        float2 e1 = __half22float2(*(const __half2*)(Eo + (size_t)cs1*1024 + col));
                        vx += cw0*e0.x + cw1*e1.x;
                        vy += cw0*e0.y + cw1*e1.y;
                    }
                    *(float2*)(Cf + crow + col) = make_float2(vx, vy);
                }
            }
        }
    }
#undef LOADST
}

// ================= flash attention: 3-stage cp.async, single barrier per tile =================
#define FTILE3 (64*72*2)
__global__ void __launch_bounds__(256) flash_attn(
    const __half* __restrict__ qkv, __half* __restrict__ att)
{
    __shared__ __align__(16) __half Ksm[3][64][72];
    __shared__ __align__(16) __half Vsm[3][64][72];
    int tid = threadIdx.x, wid = tid >> 5, lane = tid & 31;
    int bh = blockIdx.y;
    int b = bh >> 4, h = bh & 15;
    size_t plane = (size_t)NTOK*DIMM;
    const __half* qh = qkv +           (size_t)b*SLEN*DIMM + h*HDIM;
    const __half* kh = qkv + plane   + (size_t)b*SLEN*DIMM + h*HDIM;
    const __half* vh = qkv + 2*plane + (size_t)b*SLEN*DIMM + h*HDIM;
    __half* oh = att + (size_t)b*SLEN*DIMM + h*HDIM;

    int qrow0 = blockIdx.x*128 + wid*16 + (lane >> 2);
    const float SC = 0.125f * 1.44269504f;

    uint32_t qf[4][4];
    {
        const __half* qr0 = qh + (size_t)qrow0*DIMM;
        const __half* qr1 = qr0 + 8*DIMM;
        int c0 = (lane & 3)*2;
#pragma unroll
        for (int ks = 0; ks < 4; ks++) {
            qf[ks][0] = *(const uint32_t*)(qr0 + ks*16 + c0);
            qf[ks][1] = *(const uint32_t*)(qr1 + ks*16 + c0);
            qf[ks][2] = *(const uint32_t*)(qr0 + ks*16 + 8 + c0);
            qf[ks][3] = *(const uint32_t*)(qr1 + ks*16 + 8 + c0);
        }
    }

    float oacc[8][4];
#pragma unroll
    for (int nt = 0; nt < 8; nt++)
#pragma unroll
        for (int j = 0; j < 4; j++) oacc[nt][j] = 0.f;
    float M0 = -1e30f, M1 = -1e30f, L0 = 0.f, L1 = 0.f;

    int lrow = tid >> 2, lc = (tid & 3)*2;
    const __half* kSrc = kh + (size_t)lrow*DIMM + lc*8;
    const __half* vSrc = vh + (size_t)lrow*DIMM + lc*8;
    uint32_t kDst = smem_u32(&Ksm[0][lrow][lc*8]);
    uint32_t vDst = smem_u32(&Vsm[0][lrow][lc*8]);

#define FLOAD(buf_, t_) do { \
    size_t off_ = (size_t)(t_)*64*DIMM; \
    CP16(kDst + (buf_)*FTILE3,      kSrc + off_,     16); \
    CP16(kDst + (buf_)*FTILE3 + 16, kSrc + off_ + 8, 16); \
    CP16(vDst + (buf_)*FTILE3,      vSrc + off_,     16); \
    CP16(vDst + (buf_)*FTILE3 + 16, vSrc + off_ + 8, 16); \
} while (0)

    uint32_t ksBase = smem_u32(&Ksm[0][0][0]);
    uint32_t vsBase = smem_u32(&Vsm[0][0][0]);
    uint32_t sA = ksBase + (((lane>>4)&1)*8 + (lane&7))*144 + ((lane>>3)&1)*16;
    uint32_t vA = vsBase + (lane&15)*144 + (lane>>4)*16;

    FLOAD(0, 0); CPCOMMIT;
    FLOAD(1, 1); CPCOMMIT;

    const int NTILES = SLEN/64;
    for (int t = 0; t < NTILES; t++) {
        CPWAIT1;
        __syncthreads();
        if (t + 2 < NTILES) { int t2 = t + 2; FLOAD(t2 % 3, t2); }
        CPCOMMIT;
        int st = t % 3;
        uint32_t sB = sA + st*FTILE3;
        uint32_t vB = vA + st*FTILE3;

        float sacc[8][4];
#pragma unroll
        for (int nt = 0; nt < 8; nt++)
#pragma unroll
            for (int j = 0; j < 4; j++) sacc[nt][j] = 0.f;
#pragma unroll
        for (int ks = 0; ks < 4; ks++) {
#pragma unroll
            for (int nt2 = 0; nt2 < 4; nt2++) {
                uint32_t bb[4];
                LDSM_X4(bb, sB + nt2*(16*144) + ks*32);
                MMA16816(sacc[2*nt2  ], qf[ks][0], qf[ks][1], qf[ks][2], qf[ks][3], bb[0], bb[1]);
                MMA16816(sacc[2*nt2+1], qf[ks][0], qf[ks][1], qf[ks][2], qf[ks][3], bb[2], bb[3]);
            }
        }

        float mt0 = -1e30f, mt1 = -1e30f;
#pragma unroll
        for (int nt = 0; nt < 8; nt++) {
            mt0 = fmaxf(mt0, fmaxf(sacc[nt][0], sacc[nt][1]));
            mt1 = fmaxf(mt1, fmaxf(sacc[nt][2], sacc[nt][3]));
        }
        mt0 = fmaxf(mt0, __shfl_xor_sync(0xffffffffu, mt0, 1));
        mt0 = fmaxf(mt0, __shfl_xor_sync(0xffffffffu, mt0, 2));
        mt1 = fmaxf(mt1, __shfl_xor_sync(0xffffffffu, mt1, 1));
        mt1 = fmaxf(mt1, __shfl_xor_sync(0xffffffffu, mt1, 2));
        float Mn0 = fmaxf(M0, mt0), Mn1 = fmaxf(M1, mt1);
        float al0 = exp2f((M0 - Mn0)*SC), al1 = exp2f((M1 - Mn1)*SC);
        M0 = Mn0; M1 = Mn1;
        float c0 = M0*SC, c1 = M1*SC;
        uint32_t pr[8][2];
        float rs0 = 0.f, rs1 = 0.f;
#pragma unroll
        for (int nt = 0; nt < 8; nt++) {
            uint32_t h0 = f2h2(sacc[nt][0]*SC - c0, sacc[nt][1]*SC - c0);
            uint32_t h1 = f2h2(sacc[nt][2]*SC - c1, sacc[nt][3]*SC - c1);
            asm("ex2.approx.f16x2 %0, %1;" : "=r"(pr[nt][0]) : "r"(h0));
            asm("ex2.approx.f16x2 %0, %1;" : "=r"(pr[nt][1]) : "r"(h1));
            float2 p0 = __half22float2(*(__half2*)&pr[nt][0]);
            float2 p1 = __half22float2(*(__half2*)&pr[nt][1]);
            rs0 += p0.x + p0.y;
            rs1 += p1.x + p1.y;
        }
        L0 = L0*al0 + rs0;
        L1 = L1*al1 + rs1;
#pragma unroll
        for (int nt = 0; nt < 8; nt++) {
            oacc[nt][0] *= al0; oacc[nt][1] *= al0;
            oacc[nt][2] *= al1; oacc[nt][3] *= al1;
        }

#pragma unroll
        for (int ks = 0; ks < 4; ks++) {
            uint32_t a0 = pr[2*ks  ][0], a1 = pr[2*ks  ][1];
            uint32_t a2 = pr[2*ks+1][0], a3 = pr[2*ks+1][1];
#pragma unroll
            for (int nt2 = 0; nt2 < 4; nt2++) {
                uint32_t bb[4];
                LDSM_X4T(bb, vB + ks*(16*144) + nt2*32);
                MMA16816(oacc[2*nt2  ], a0, a1, a2, a3, bb[0], bb[1]);
                MMA16816(oacc[2*nt2+1], a0, a1, a2, a3, bb[2], bb[3]);
            }
        }
    }
#undef FLOAD

    L0 += __shfl_xor_sync(0xffffffffu, L0, 1);
    L0 += __shfl_xor_sync(0xffffffffu, L0, 2);
    L1 += __shfl_xor_sync(0xffffffffu, L1, 1);
    L1 += __shfl_xor_sync(0xffffffffu, L1, 2);
    float inv0 = 1.f / L0, inv1 = 1.f / L1;
    __half* or0 = oh + (size_t)qrow0*DIMM;
    __half* or1 = or0 + 8*DIMM;
#pragma unroll
    for (int nt = 0; nt < 8; nt++) {
        int col = nt*8 + (lane & 3)*2;
        *(uint32_t*)(or0 + col) = f2h2(oacc[nt][0]*inv0, oacc[nt][1]*inv0);
        *(uint32_t*)(or1 + col) = f2h2(oacc[nt][2]*inv1, oacc[nt][3]*inv1);
    }
}

// ================= fused weight conversion =================
struct CvtArgs {
    const float* s[10];
    __half* d[10];
    int sb[10];
};
__global__ void cvt_all(CvtArgs a) {
    int b = blockIdx.x;
    int r = 0;
#pragma unroll
    for (int i = 1; i < 10; i++) r += (b >= a.sb[i]);
    const float* src = a.s[r];
    __half* dst = a.d[r];
    int off = (b - a.sb[r])*2048 + threadIdx.x*8;
    float4 f0 = *(const float4*)(src + off);
    float4 f1 = *(const float4*)(src + off + 4);
    uint4 o;
    o.x = f2h2(f0.x, f0.y); o.y = f2h2(f0.z, f0.w);
    o.z = f2h2(f1.x, f1.y); o.w = f2h2(f1.z, f1.w);
    *(uint4*)(dst + off) = o;
}

// ================= elementwise kernels =================
__global__ void rmsnorm_kernel(const float* __restrict__ x, const float* __restrict__ w,
                               __half* __restrict__ outh, float* __restrict__ outf,
                               int* __restrict__ zc) {
    int row = blockIdx.x;
    if (zc && row == 0 && threadIdx.x < NEXP) zc[threadIdx.x] = 0;
    const float* xr = x + (size_t)row*DIMM;
    float v[4]; float s = 0.f;
#pragma unroll
    for (int i = 0; i < 4; i++) { v[i] = xr[threadIdx.x + i*256]; s += v[i]*v[i]; }
    __shared__ float red[8];
#pragma unroll
    for (int o = 16; o > 0; o >>= 1) s += __shfl_xor_sync(0xffffffffu, s, o);
    if ((threadIdx.x & 31) == 0) red[threadIdx.x >> 5] = s;
    __syncthreads();
    if (threadIdx.x < 8) {
        float t = red[threadIdx.x];
#pragma unroll
        for (int o = 4; o > 0; o >>= 1) t += __shfl_xor_sync(0xffu, t, o);
        if (threadIdx.x == 0) red[0] = t;
    }
    __syncthreads();
    float r = rsqrtf(red[0] / (float)DIMM + EPSV);
#pragma unroll
    for (int i = 0; i < 4; i++) {
        int c = threadIdx.x + i*256;
        float val = v[i]*r*w[c];
        outh[(size_t)row*DIMM + c] = __float2half(val);
        if (outf) outf[(size_t)row*DIMM + c] = val;
    }
}

__global__ void gate_topk(const float* __restrict__ hn, const float* __restrict__ gw,
                          int* __restrict__ tidx, float* __restrict__ tw,
                          int* __restrict__ counts) {
    int n = blockIdx.x;
    int w = threadIdx.x >> 5, lane = threadIdx.x & 31;
    const float* x = hn + (size_t)n*DIMM;
    const float* g = gw + (size_t)w*DIMM;
    float s = 0.f;
    for (int i = lane; i < DIMM; i += 32) s += x[i]*g[i];
#pragma unroll
    for (int o = 16; o > 0; o >>= 1) s += __shfl_xor_sync(0xffffffffu, s, o);
    __shared__ float sc[NEXP];
    if (lane == 0) sc[w] = s;
    __syncthreads();
    if (threadIdx.x == 0) {
        float mx = sc[0];
        for (int e = 1; e < NEXP; e++) mx = fmaxf(mx, sc[e]);
        float p[NEXP]; float sum = 0.f;
        for (int e = 0; e < NEXP; e++) { p[e] = expf(sc[e]-mx); sum += p[e]; }
        for (int e = 0; e < NEXP; e++) p[e] /= sum;
        int i0 = 0;
        for (int e = 1; e < NEXP; e++) if (p[e] > p[i0]) i0 = e;
        int i1 = -1;
        for (int e = 0; e < NEXP; e++)
            if (e != i0 && (i1 < 0 || p[e] > p[i1])) i1 = e;
        tidx[n*2]   = i0; tidx[n*2+1] = i1;
        tw[n*2]     = p[i0]; tw[n*2+1] = p[i1];
        atomicAdd(&counts[i0], 1);
        atomicAdd(&counts[i1], 1);
    }
}

__global__ void prefix_kernel(const int* __restrict__ counts, int* __restrict__ offs,
                              int* __restrict__ fill) {
    if (threadIdx.x == 0) {
        int a = 0;
        for (int e = 0; e < NEXP; e++) { offs[e] = a; a += counts[e]; }
        offs[NEXP] = a;
    }
    if (threadIdx.x < NEXP) fill[threadIdx.x] = 0;
}

__global__ void scatter_kernel(const int* __restrict__ tidx,
                               const int* __restrict__ offs, int* __restrict__ fill,
                               int* __restrict__ tok, int* __restrict__ smap) {
    int n = blockIdx.x*blockDim.x + threadIdx.x;
    if (n >= NTOK) return;
#pragma unroll
    for (int j = 0; j < TOPK; j++) {
        int e = tidx[n*2+j];
        int slot = offs[e] + atomicAdd(&fill[e], 1);
        tok[slot] = n;
        smap[n*2+j] = slot;
    }
}

__global__ void silu_mul_hh(const __half* __restrict__ a, const __half* __restrict__ b,
                            __half* __restrict__ o, size_t n) {
    size_t i = ((size_t)blockIdx.x*blockDim.x + threadIdx.x)*8;
    if (i >= n) return;
    uint4 av = *(const uint4*)(a + i);
    uint4 bv = *(const uint4*)(b + i);
    uint4 ov;
    uint32_t* ap = (uint32_t*)&av;
    uint32_t* bp = (uint32_t*)&bv;
    uint32_t* op = (uint32_t*)&ov;
#pragma unroll
    for (int j = 0; j < 4; j++) {
        float2 af = __half22float2(*(__half2*)&ap[j]);
        float2 bf = __half22float2(*(__half2*)&bp[j]);
        float r0 = af.x / (1.f + __expf(-af.x)) * bf.x;
        float r1 = af.y / (1.f + __expf(-af.y)) * bf.y;
        op[j] = f2h2(r0, r1);
    }
    *(uint4*)(o + i) = ov;
}

// ================= launcher =================
extern "C" void kernel_launch(void* const* d_in, const int* in_sizes, int n_in,
                              void* d_out, int out_size) {
    (void)in_sizes; (void)n_in; (void)out_size;
    const float* x     = (const float*)d_in[0];
    const float* freqs = (const float*)d_in[1];
    const float* att_w = (const float*)d_in[2];
    const float* wq    = (const float*)d_in[3];
    const float* wk    = (const float*)d_in[4];
    const float* wv    = (const float*)d_in[5];
    const float* wo    = (const float*)d_in[6];
    const float* ffn_w = (const float*)d_in[7];
    const float* gw    = (const float*)d_in[8];
    const float* ew1   = (const float*)d_in[9];
    const float* ew2   = (const float*)d_in[10];
    const float* ew3   = (const float*)d_in[11];
    const float* sw1   = (const float*)d_in[12];
    const float* sw2   = (const float*)d_in[13];
    const float* sw3   = (const float*)d_in[14];
    float* out = (float*)d_out;

    __half *wqkvh,*woh,*e13h,*e2h,*s13wh,*s2wh,*xnh,*qkvh,*atth,*hnh;
    __half *h13h,*g13h,*s13hh,*s13h,*eoh;
    float *h,*hn32,*tw;
    int *tidx,*counts,*offs,*fill,*tok,*smap;
    cudaGetSymbolAddress((void**)&wqkvh, g_wqkvh);
    cudaGetSymbolAddress((void**)&woh,   g_woh);
    cudaGetSymbolAddress((void**)&e13h,  g_e13h);
    cudaGetSymbolAddress((void**)&e2h,   g_e2h);
    cudaGetSymbolAddress((void**)&s13wh, g_s13wh);
    cudaGetSymbolAddress((void**)&s2wh,  g_s2wh);
    cudaGetSymbolAddress((void**)&xnh,   g_xnh);
    cudaGetSymbolAddress((void**)&qkvh,  g_qkvh);
    cudaGetSymbolAddress((void**)&atth,  g_atth);
    cudaGetSymbolAddress((void**)&hnh,   g_hnh);
    cudaGetSymbolAddress((void**)&h13h,  g_h13h);
    cudaGetSymbolAddress((void**)&g13h,  g_g13h);
    cudaGetSymbolAddress((void**)&s13hh, g_s13hh);
    cudaGetSymbolAddress((void**)&s13h,  g_s13h);
    cudaGetSymbolAddress((void**)&eoh,   g_eoh);
    cudaGetSymbolAddress((void**)&h,     g_h);
    cudaGetSymbolAddress((void**)&hn32,  g_hn32);
    cudaGetSymbolAddress((void**)&tidx,  g_topk_idx);
    cudaGetSymbolAddress((void**)&tw,    g_topk_w);
    cudaGetSymbolAddress((void**)&counts, g_counts);
    cudaGetSymbolAddress((void**)&offs,   g_offsets);
    cudaGetSymbolAddress((void**)&fill,   g_fill);
    cudaGetSymbolAddress((void**)&tok,    g_tok_idx);
    cudaGetSymbolAddress((void**)&smap,   g_slot_map);

    cudaFuncSetAttribute(gemm2<false,false,false,true ,true ,false>, cudaFuncAttributeMaxDynamicSharedMemorySize, SMEMB);
    cudaFuncSetAttribute(gemm2<false,false,true, false,false,false>, cudaFuncAttributeMaxDynamicSharedMemorySize, SMEMB);
    cudaFuncSetAttribute(gemm2<true, true, false,true ,false,false>, cudaFuncAttributeMaxDynamicSharedMemorySize, SMEMB);
    cudaFuncSetAttribute(gemm2<false,true, false,true ,false,false>, cudaFuncAttributeMaxDynamicSharedMemorySize, SMEMB);
    cudaFuncSetAttribute(gemm2<false,false,false,true ,false,false>, cudaFuncAttributeMaxDynamicSharedMemorySize, SMEMB);
    cudaFuncSetAttribute(gemm2<false,false,true, false,false,true >, cudaFuncAttributeMaxDynamicSharedMemorySize, SMEMB);

    const int T = 256;
    const int WQN = DIMM*DIMM;
    const int EWN = DIMM*HIDD;

    // ---- fused weight conversion ----
    {
        CvtArgs a;
        a.s[0]=wq;  a.d[0]=wqkvh;         a.sb[0]=0;
        a.s[1]=wk;  a.d[1]=wqkvh+WQN;     a.sb[1]=512;
        a.s[2]=wv;  a.d[2]=wqkvh+2*WQN;   a.sb[2]=1024;
        a.s[3]=wo;  a.d[3]=woh;           a.sb[3]=1536;
        a.s[4]=ew1; a.d[4]=e13h;                        a.sb[4]=2048;
        a.s[5]=ew3; a.d[5]=e13h+(size_t)NEXP*EWN;       a.sb[5]=6144;
        a.s[6]=ew2; a.d[6]=e2h;                         a.sb[6]=10240;
        a.s[7]=sw1; a.d[7]=s13wh;         a.sb[7]=14336;
        a.s[8]=sw3; a.d[8]=s13wh+EWN;     a.sb[8]=14848;
        a.s[9]=sw2; a.d[9]=s2wh;          a.sb[9]=15360;
        cvt_all<<<15872, T>>>(a);
    }

    // 1) attention pre-norm
    rmsnorm_kernel<<<NTOK, T>>>(x, att_w, xnh, nullptr, nullptr);

    // 2) QKV with fused RoPE
    gemm2<false,false,false,true,true,false><<<dim3(32,8,3), T, SMEMB>>>(
        xnh, wqkvh, qkvh, nullptr, NTOK, 1.f,
        0, (long long)DIMM*DIMM, (long long)NTOK*DIMM, 0, nullptr, nullptr,
        freqs, nullptr, nullptr, nullptr);

    // 3) flash attention
    flash_attn<<<dim3(SLEN/128, BSZ*NHEAD), T>>>(qkvh, atth);

    // 4) h = x + att @ wo
    gemm2<false,false,true,false,false,false><<<dim3(32,8,1), T, SMEMB>>>(
        atth, woh, h, x, NTOK, 1.f, 0, 0, 0, 0, nullptr, nullptr,
        nullptr, nullptr, nullptr, nullptr);

    // 5) ffn pre-norm (also zeroes gate counts)
    rmsnorm_kernel<<<NTOK, T>>>(h, ffn_w, hnh, hn32, counts);

    // 6) gate + routing
    gate_topk<<<NTOK, T>>>(hn32, gw, tidx, tw, counts);
    prefix_kernel<<<1, 32>>>(counts, offs, fill);
    scatter_kernel<<<(NTOK + T - 1)/T, T>>>(tidx, offs, fill, tok, smap);

    // 7) experts
    gemm2<true,true,false,true,false,false><<<dim3(32,8,16), T, SMEMB>>>(
        hnh, e13h, h13h, nullptr, 0, 1.f,
        0, (long long)EWN, 0, (long long)NSLOT*HIDD, tok, offs,
        nullptr, nullptr, nullptr, nullptr);
    silu_mul_hh<<<(unsigned)(((size_t)NSLOT*HIDD)/2048), T>>>(
        h13h, h13h + (size_t)NSLOT*HIDD, g13h, (size_t)NSLOT*HIDD);
    gemm2<false,true,false,true,false,false><<<dim3(32,8,NEXP), T, SMEMB>>>(
        g13h, e2h, eoh, nullptr, 0, 1.f,
        0, (long long)EWN, 0, 0, nullptr, offs,
        nullptr, nullptr, nullptr, nullptr);

    // 8) shared expert
    gemm2<false,false,false,true,false,false><<<dim3(32,8,2), T, SMEMB>>>(
        hnh, s13wh, s13hh, nullptr, NTOK, 1.f,
        0, (long long)EWN, (long long)NTOK*HIDD, 0, nullptr, nullptr,
        nullptr, nullptr, nullptr, nullptr);
    silu_mul_hh<<<(unsigned)(((size_t)NTOK*HIDD)/2048), T>>>(
        s13hh, s13hh + (size_t)NTOK*HIDD, s13h, (size_t)NTOK*HIDD);

    // 9) final: out = h + s13 @ sw2 + routed combine (fused)
    gemm2<false,false,true,false,false,true><<<dim3(32,8,1), T, SMEMB>>>(
        s13h, s2wh, out, h, NTOK, 1.f, 0, 0, 0, 0, nullptr, nullptr,
        nullptr, eoh, smap, tw);
}

// round 12
// speedup vs baseline: 1.3038x; 1.3038x over previous
#include <cuda_runtime.h>
#include <cuda_fp16.h>
#include <math.h>
#include <stdint.h>

#define DIMM 1024
#define NHEAD 16
#define HDIM 64
#define SLEN 2048
#define BSZ 2
#define NTOK (BSZ*SLEN)          // 4096
#define NEXP 8
#define TOPK 2
#define HIDD 1024
#define NSLOT (NTOK*TOPK)        // 8192
#define EPSV 1e-6f

// GEMM pipeline constants (BK=32, 4 stages — the measured-best config)
#define AST 40
#define BST 136
#define A_STAGE (128*AST)
#define B_STAGE (32*BST)
#define STAGES 4
#define SMEMB (STAGES*(A_STAGE+B_STAGE)*2)   // 75776 B -> 2 CTAs/SM

// ================= scratch =================
__device__ __half g_wqkvh[(size_t)3*DIMM*DIMM];
__device__ __half g_woh[(size_t)DIMM*DIMM];
__device__ __half g_e13h[(size_t)2*NEXP*DIMM*HIDD];
__device__ __half g_e2h[(size_t)NEXP*HIDD*DIMM];
__device__ __half g_s13wh[(size_t)2*DIMM*HIDD];
__device__ __half g_s2wh[(size_t)HIDD*DIMM];
__device__ __half g_xnh[(size_t)NTOK*DIMM];
__device__ __half g_qkvh[(size_t)3*NTOK*DIMM];
__device__ __half g_atth[(size_t)NTOK*DIMM];
__device__ __half g_hnh[(size_t)NTOK*DIMM];
__device__ __half g_h13h[(size_t)2*NSLOT*HIDD];
__device__ __half g_g13h[(size_t)NSLOT*HIDD];
__device__ __half g_s13hh[(size_t)2*NTOK*HIDD];
__device__ __half g_s13h[(size_t)NTOK*HIDD];
__device__ __half g_eoh[(size_t)NSLOT*DIMM];
__device__ float g_h[(size_t)NTOK*DIMM];
__device__ float g_hn32[(size_t)NTOK*DIMM];
__device__ int   g_topk_idx[NTOK*TOPK];
__device__ float g_topk_w [NTOK*TOPK];
__device__ int   g_counts[NEXP];
__device__ int   g_offsets[NEXP+1];
__device__ int   g_fill[NEXP];
__device__ int   g_tok_idx[NSLOT];
__device__ int   g_slot_map[NTOK*TOPK];

__device__ __forceinline__ uint32_t f2h2(float lo, float hi) {
    __half2 h = __floats2half2_rn(lo, hi);
    return *reinterpret_cast<uint32_t*>(&h);
}
__device__ __forceinline__ uint32_t smem_u32(const void* p) {
    uint32_t a;
    asm("{ .reg .u64 t; cvta.to.shared.u64 t, %1; cvt.u32.u64 %0, t; }" : "=r"(a) : "l"(p));
    return a;
}

#define MMA16816(acc, a0,a1,a2,a3, b0,b1) \
    asm volatile( \
        "mma.sync.aligned.m16n8k16.row.col.f32.f16.f16.f32 " \
        "{%0,%1,%2,%3}, {%4,%5,%6,%7}, {%8,%9}, {%0,%1,%2,%3};" \
        : "+f"((acc)[0]), "+f"((acc)[1]), "+f"((acc)[2]), "+f"((acc)[3]) \
        : "r"(a0), "r"(a1), "r"(a2), "r"(a3), "r"(b0), "r"(b1))

#define LDSM_X4(r, addr) \
    asm volatile("ldmatrix.sync.aligned.m8n8.x4.shared.b16 {%0,%1,%2,%3}, [%4];" \
        : "=r"((r)[0]),"=r"((r)[1]),"=r"((r)[2]),"=r"((r)[3]) : "r"(addr))
#define LDSM_X4T(r, addr) \
    asm volatile("ldmatrix.sync.aligned.m8n8.x4.trans.shared.b16 {%0,%1,%2,%3}, [%4];" \
        : "=r"((r)[0]),"=r"((r)[1]),"=r"((r)[2]),"=r"((r)[3]) : "r"(addr))

#define CP16(dst, src, sz) \
    asm volatile("cp.async.cg.shared.global [%0], [%1], 16, %2;" \
        :: "r"(dst), "l"(src), "r"(sz) : "memory")
#define CPCOMMIT asm volatile("cp.async.commit_group;" ::: "memory")
#define CPWAIT2  asm volatile("cp.async.wait_group 2;" ::: "memory")
#define CPWAIT1  asm volatile("cp.async.wait_group 1;" ::: "memory")
#define CPWAIT0  asm volatile("cp.async.wait_group 0;" ::: "memory")

// ================= GEMM: half A [M,1024], half B [1024,1024] =================
// BK=32 chunks, 4-stage cp.async pipeline (R10 config).
template<bool GATHER, bool GROUPED, bool RESID, bool HALFOUT, bool ROPE, bool COMBINE>
__global__ void __launch_bounds__(256) gemm2(
    const __half* __restrict__ A, const __half* __restrict__ B,
    void* __restrict__ Cv, const float* __restrict__ Rr,
    int M, float scale,
    long long sAo, long long sBo, long long sCo, long long sCg,
    const int* __restrict__ gidx, const int* __restrict__ offsets,
    const float* __restrict__ Fq, const __half* __restrict__ Eo,
    const int* __restrict__ smap, const float* __restrict__ tw)
{
    extern __shared__ __half smx[];
    const int LDA = 1024;
    int tid = threadIdx.x, lane = tid & 31, wid = tid >> 5;
    int warpM = wid & 3, warpN = wid >> 2;
    int z = blockIdx.z;

    float* Cf = (float*)Cv;
    __half* Ch = (__half*)Cv;

    int Mz = M, seg0 = 0;
    if (GROUPED) {
        int e = z & 7;
        seg0 = offsets[e]; Mz = offsets[e+1] - seg0;
        B  += (size_t)z * sBo;
        if (HALFOUT) Ch += (size_t)(z >> 3) * sCg;
        else         Cf += (size_t)(z >> 3) * sCg;
    } else {
        A += (size_t)z * sAo;
        B += (size_t)z * sBo;
        if (HALFOUT) Ch += (size_t)z * sCo; else Cf += (size_t)z * sCo;
        if (RESID) Rr += (size_t)z * sCo;
    }
    int m0 = blockIdx.x * 128;
    if (GROUPED && m0 >= Mz) return;
    int n0 = blockIdx.y * 128;

    uint32_t AsB = smem_u32(smx);
    uint32_t BsB = AsB + STAGES*A_STAGE*2;

    int arow = tid >> 1, acH = (tid & 1)*16;
    bool aOK = (!GROUPED) || ((m0 + arow) < Mz);
    long long grow = 0;
    if (aOK) grow = GATHER ? (long long)gidx[seg0 + m0 + arow]
                  : (GROUPED ? (long long)(seg0 + m0 + arow) : (long long)(m0 + arow));
    const __half* aP = A + (size_t)grow*LDA + acH;
    uint32_t aD = AsB + (arow*AST + acH)*2;
    int aSz = aOK ? 16 : 0;

    int brow = tid >> 3, bH = (tid & 7)*16;
    const __half* bP = B + (size_t)brow*LDA + n0 + bH;
    uint32_t bD = BsB + (brow*BST + bH)*2;

#define LOADST(s_, c_) do { \
    int kt_ = (c_)*32; \
    CP16(aD + (s_)*(A_STAGE*2),      aP + kt_,     aSz); \
    CP16(aD + (s_)*(A_STAGE*2) + 16, aP + kt_ + 8, aSz); \
    CP16(bD + (s_)*(B_STAGE*2),      bP + (size_t)kt_*LDA,     16); \
    CP16(bD + (s_)*(B_STAGE*2) + 16, bP + (size_t)kt_*LDA + 8, 16); \
} while (0)

    float acc[2][8][4];
#pragma unroll
    for (int mt = 0; mt < 2; mt++)
#pragma unroll
        for (int nt = 0; nt < 8; nt++)
#pragma unroll
            for (int j = 0; j < 4; j++) acc[mt][nt][j] = 0.f;

    uint32_t aAddr = AsB + ((warpM*32 + (lane & 15))*AST + ((lane >> 4) & 1)*8)*2;
    uint32_t bAddr = BsB + ((lane & 15)*BST + warpN*64 + ((lane >> 4) & 1)*8)*2;

    LOADST(0, 0); CPCOMMIT;
    LOADST(1, 1); CPCOMMIT;
    LOADST(2, 2); CPCOMMIT;

    for (int c = 0; c < 32; c++) {
        CPWAIT2;
        __syncthreads();
        int st = c & 3;
        uint32_t aS = aAddr + st*(A_STAGE*2);
        uint32_t bS = bAddr + st*(B_STAGE*2);
#pragma unroll
        for (int ks = 0; ks < 2; ks++) {
            uint32_t af0[4], af1[4];
            LDSM_X4(af0, aS + ks*32);
            LDSM_X4(af1, aS + ks*32 + 16*AST*2);
            uint32_t bf[4][4];
#pragma unroll
            for (int nt2 = 0; nt2 < 4; nt2++)
                LDSM_X4T(bf[nt2], bS + ks*(16*BST*2) + nt2*32);
#pragma unroll
            for (int nt2 = 0; nt2 < 4; nt2++) {
                MMA16816(acc[0][2*nt2  ], af0[0],af0[1],af0[2],af0[3], bf[nt2][0],bf[nt2][1]);
                MMA16816(acc[0][2*nt2+1], af0[0],af0[1],af0[2],af0[3], bf[nt2][2],bf[nt2][3]);
                MMA16816(acc[1][2*nt2  ], af1[0],af1[1],af1[2],af1[3], bf[nt2][0],bf[nt2][1]);
                MMA16816(acc[1][2*nt2+1], af1[0],af1[1],af1[2],af1[3], bf[nt2][2],bf[nt2][3]);
            }
        }
        if (c + 3 < 32) { int c2 = c + 3; LOADST(c2 & 3, c2); }
        CPCOMMIT;
    }

#pragma unroll
    for (int mt = 0; mt < 2; mt++) {
        int rb = m0 + warpM*32 + mt*16 + (lane >> 2);
#pragma unroll
        for (int hh = 0; hh < 2; hh++) {
            int r = rb + hh*8;
            if (GROUPED && r >= Mz) continue;
            size_t crow = (size_t)((GROUPED ? seg0 : 0) + r) * 1024;
            int cs0 = 0, cs1 = 0; float cw0 = 0.f, cw1 = 0.f;
            if (COMBINE) {
                cs0 = smap[r*2]; cs1 = smap[r*2+1];
                cw0 = tw[r*2];   cw1 = tw[r*2+1];
            }
#pragma unroll
            for (int nt = 0; nt < 8; nt++) {
                int col = n0 + warpN*64 + nt*8 + (lane & 3)*2;
                float vx = acc[mt][nt][hh*2+0]*scale;
                float vy = acc[mt][nt][hh*2+1]*scale;
                if (ROPE) {
                    if (z < 2) {
                        int s = r & (SLEN-1);
                        int p = (col & 63) >> 1;
                        float cc = Fq[(s*(HDIM/2) + p)*2 + 0];
                        float sn = Fq[(s*(HDIM/2) + p)*2 + 1];
                        float rx = vx*cc - vy*sn;
                        float ry = vx*sn + vy*cc;
                        vx = rx; vy = ry;
                    }
                }
                if (HALFOUT) {
                    *(uint32_t*)(Ch + crow + col) = f2h2(vx, vy);
                } else {
                    if (RESID) {
                        float2 rv = *(const float2*)(Rr + crow + col);
                        vx += rv.x; vy += rv.y;
                    }
                    if (COMBINE) {
                        float2 e0 = __half22float2(*(const __half2*)(Eo + (size_t)cs0*1024 + col));
                        float2 e1 = __half22float2(*(const __half2*)(Eo + (size_t)cs1*1024 + col));
                        vx += cw0*e0.x + cw1*e1.x;
                        vy += cw0*e0.y + cw1*e1.y;
                    }
                    *(float2*)(Cf + crow + col) = make_float2(vx, vy);
                }
            }
        }
    }
#undef LOADST
}

// ================= flash attention: 3-stage cp.async, single barrier per tile =================
#define FTILE3 (64*72*2)
__global__ void __launch_bounds__(256) flash_attn(
    const __half* __restrict__ qkv, __half* __restrict__ att)
{
    __shared__ __align__(16) __half Ksm[3][64][72];
    __shared__ __align__(16) __half Vsm[3][64][72];
    int tid = threadIdx.x, wid = tid >> 5, lane = tid & 31;
    int bh = blockIdx.y;
    int b = bh >> 4, h = bh & 15;
    size_t plane = (size_t)NTOK*DIMM;
    const __half* qh = qkv +           (size_t)b*SLEN*DIMM + h*HDIM;
    const __half* kh = qkv + plane   + (size_t)b*SLEN*DIMM + h*HDIM;
    const __half* vh = qkv + 2*plane + (size_t)b*SLEN*DIMM + h*HDIM;
    __half* oh = att + (size_t)b*SLEN*DIMM + h*HDIM;

    int qrow0 = blockIdx.x*128 + wid*16 + (lane >> 2);
    const float SC = 0.125f * 1.44269504f;

    uint32_t qf[4][4];
    {
        const __half* qr0 = qh + (size_t)qrow0*DIMM;
        const __half* qr1 = qr0 + 8*DIMM;
        int c0 = (lane & 3)*2;
#pragma unroll
        for (int ks = 0; ks < 4; ks++) {
            qf[ks][0] = *(const uint32_t*)(qr0 + ks*16 + c0);
            qf[ks][1] = *(const uint32_t*)(qr1 + ks*16 + c0);
            qf[ks][2] = *(const uint32_t*)(qr0 + ks*16 + 8 + c0);
            qf[ks][3] = *(const uint32_t*)(qr1 + ks*16 + 8 + c0);
        }
    }

    float oacc[8][4];
#pragma unroll
    for (int nt = 0; nt < 8; nt++)
#pragma unroll
        for (int j = 0; j < 4; j++) oacc[nt][j] = 0.f;
    float M0 = -1e30f, M1 = -1e30f, L0 = 0.f, L1 = 0.f;

    int lrow = tid >> 2, lc = (tid & 3)*2;
    const __half* kSrc = kh + (size_t)lrow*DIMM + lc*8;
    const __half* vSrc = vh + (size_t)lrow*DIMM + lc*8;
    uint32_t kDst = smem_u32(&Ksm[0][lrow][lc*8]);
    uint32_t vDst = smem_u32(&Vsm[0][lrow][lc*8]);

#define FLOAD(buf_, t_) do { \
    size_t off_ = (size_t)(t_)*64*DIMM; \
    CP16(kDst + (buf_)*FTILE3,      kSrc + off_,     16); \
    CP16(kDst + (buf_)*FTILE3 + 16, kSrc + off_ + 8, 16); \
    CP16(vDst + (buf_)*FTILE3,      vSrc + off_,     16); \
    CP16(vDst + (buf_)*FTILE3 + 16, vSrc + off_ + 8, 16); \
} while (0)

    uint32_t ksBase = smem_u32(&Ksm[0][0][0]);
    uint32_t vsBase = smem_u32(&Vsm[0][0][0]);
    uint32_t sA = ksBase + (((lane>>4)&1)*8 + (lane&7))*144 + ((lane>>3)&1)*16;
    uint32_t vA = vsBase + (lane&15)*144 + (lane>>4)*16;

    FLOAD(0, 0); CPCOMMIT;
    FLOAD(1, 1); CPCOMMIT;

    const int NTILES = SLEN/64;
    for (int t = 0; t < NTILES; t++) {
        CPWAIT1;
        __syncthreads();
        if (t + 2 < NTILES) { int t2 = t + 2; FLOAD(t2 % 3, t2); }
        CPCOMMIT;
        int st = t % 3;
        uint32_t sB = sA + st*FTILE3;
        uint32_t vB = vA + st*FTILE3;

        float sacc[8][4];
#pragma unroll
        for (int nt = 0; nt < 8; nt++)
#pragma unroll
            for (int j = 0; j < 4; j++) sacc[nt][j] = 0.f;
#pragma unroll
        for (int ks = 0; ks < 4; ks++) {
#pragma unroll
            for (int nt2 = 0; nt2 < 4; nt2++) {
                uint32_t bb[4];
                LDSM_X4(bb, sB + nt2*(16*144) + ks*32);
                MMA16816(sacc[2*nt2  ], qf[ks][0], qf[ks][1], qf[ks][2], qf[ks][3], bb[0], bb[1]);
                MMA16816(sacc[2*nt2+1], qf[ks][0], qf[ks][1], qf[ks][2], qf[ks][3], bb[2], bb[3]);
            }
        }

        float mt0 = -1e30f, mt1 = -1e30f;
#pragma unroll
        for (int nt = 0; nt < 8; nt++) {
            mt0 = fmaxf(mt0, fmaxf(sacc[nt][0], sacc[nt][1]));
            mt1 = fmaxf(mt1, fmaxf(sacc[nt][2], sacc[nt][3]));
        }
        mt0 = fmaxf(mt0, __shfl_xor_sync(0xffffffffu, mt0, 1));
        mt0 = fmaxf(mt0, __shfl_xor_sync(0xffffffffu, mt0, 2));
        mt1 = fmaxf(mt1, __shfl_xor_sync(0xffffffffu, mt1, 1));
        mt1 = fmaxf(mt1, __shfl_xor_sync(0xffffffffu, mt1, 2));
        float Mn0 = fmaxf(M0, mt0), Mn1 = fmaxf(M1, mt1);
        float al0 = exp2f((M0 - Mn0)*SC), al1 = exp2f((M1 - Mn1)*SC);
        M0 = Mn0; M1 = Mn1;
        float c0 = M0*SC, c1 = M1*SC;
        uint32_t pr[8][2];
        float rs0 = 0.f, rs1 = 0.f;
#pragma unroll
        for (int nt = 0; nt < 8; nt++) {
            uint32_t h0 = f2h2(sacc[nt][0]*SC - c0, sacc[nt][1]*SC - c0);
            uint32_t h1 = f2h2(sacc[nt][2]*SC - c1, sacc[nt][3]*SC - c1);
            asm("ex2.approx.f16x2 %0, %1;" : "=r"(pr[nt][0]) : "r"(h0));
            asm("ex2.approx.f16x2 %0, %1;" : "=r"(pr[nt][1]) : "r"(h1));
            float2 p0 = __half22float2(*(__half2*)&pr[nt][0]);
            float2 p1 = __half22float2(*(__half2*)&pr[nt][1]);
            rs0 += p0.x + p0.y;
            rs1 += p1.x + p1.y;
        }
        L0 = L0*al0 + rs0;
        L1 = L1*al1 + rs1;
#pragma unroll
        for (int nt = 0; nt < 8; nt++) {
            oacc[nt][0] *= al0; oacc[nt][1] *= al0;
            oacc[nt][2] *= al1; oacc[nt][3] *= al1;
        }

#pragma unroll
        for (int ks = 0; ks < 4; ks++) {
            uint32_t a0 = pr[2*ks  ][0], a1 = pr[2*ks  ][1];
            uint32_t a2 = pr[2*ks+1][0], a3 = pr[2*ks+1][1];
#pragma unroll
            for (int nt2 = 0; nt2 < 4; nt2++) {
                uint32_t bb[4];
                LDSM_X4T(bb, vB + ks*(16*144) + nt2*32);
                MMA16816(oacc[2*nt2  ], a0, a1, a2, a3, bb[0], bb[1]);
                MMA16816(oacc[2*nt2+1], a0, a1, a2, a3, bb[2], bb[3]);
            }
        }
    }
#undef FLOAD

    L0 += __shfl_xor_sync(0xffffffffu, L0, 1);
    L0 += __shfl_xor_sync(0xffffffffu, L0, 2);
    L1 += __shfl_xor_sync(0xffffffffu, L1, 1);
    L1 += __shfl_xor_sync(0xffffffffu, L1, 2);
    float inv0 = 1.f / L0, inv1 = 1.f / L1;
    __half* or0 = oh + (size_t)qrow0*DIMM;
    __half* or1 = or0 + 8*DIMM;
#pragma unroll
    for (int nt = 0; nt < 8; nt++) {
        int col = nt*8 + (lane & 3)*2;
        *(uint32_t*)(or0 + col) = f2h2(oacc[nt][0]*inv0, oacc[nt][1]*inv0);
        *(uint32_t*)(or1 + col) = f2h2(oacc[nt][2]*inv1, oacc[nt][3]*inv1);
    }
}

// ================= fused weight conversion =================
struct CvtArgs {
    const float* s[10];
    __half* d[10];
    int sb[10];
};
__global__ void cvt_all(CvtArgs a) {
    int b = blockIdx.x;
    int r = 0;
#pragma unroll
    for (int i = 1; i < 10; i++) r += (b >= a.sb[i]);
    const float* src = a.s[r];
    __half* dst = a.d[r];
    int off = (b - a.sb[r])*2048 + threadIdx.x*8;
    float4 f0 = *(const float4*)(src + off);
    float4 f1 = *(const float4*)(src + off + 4);
    uint4 o;
    o.x = f2h2(f0.x, f0.y); o.y = f2h2(f0.z, f0.w);
    o.z = f2h2(f1.x, f1.y); o.w = f2h2(f1.z, f1.w);
    *(uint4*)(dst + off) = o;
}

// ================= elementwise kernels =================
__global__ void rmsnorm_kernel(const float* __restrict__ x, const float* __restrict__ w,
                               __half* __restrict__ outh, float* __restrict__ outf,
                               int* __restrict__ zc) {
    int row = blockIdx.x;
    if (zc && row == 0 && threadIdx.x < NEXP) zc[threadIdx.x] = 0;
    const float* xr = x + (size_t)row*DIMM;
    float v[4]; float s = 0.f;
#pragma unroll
    for (int i = 0; i < 4; i++) { v[i] = xr[threadIdx.x + i*256]; s += v[i]*v[i]; }
    __shared__ float red[8];
#pragma unroll
    for (int o = 16; o > 0; o >>= 1) s += __shfl_xor_sync(0xffffffffu, s, o);
    if ((threadIdx.x & 31) == 0) red[threadIdx.x >> 5] = s;
    __syncthreads();
    if (threadIdx.x < 8) {
        float t = red[threadIdx.x];
#pragma unroll
        for (int o = 4; o > 0; o >>= 1) t += __shfl_xor_sync(0xffu, t, o);
        if (threadIdx.x == 0) red[0] = t;
    }
    __syncthreads();
    float r = rsqrtf(red[0] / (float)DIMM + EPSV);
#pragma unroll
    for (int i = 0; i < 4; i++) {
        int c = threadIdx.x + i*256;
        float val = v[i]*r*w[c];
        outh[(size_t)row*DIMM + c] = __float2half(val);
        if (outf) outf[(size_t)row*DIMM + c] = val;
    }
}

__global__ void gate_topk(const float* __restrict__ hn, const float* __restrict__ gw,
                          int* __restrict__ tidx, float* __restrict__ tw,
                          int* __restrict__ counts) {
    int n = blockIdx.x;
    int w = threadIdx.x >> 5, lane = threadIdx.x & 31;
    const float* x = hn + (size_t)n*DIMM;
    const float* g = gw + (size_t)w*DIMM;
    float s = 0.f;
    for (int i = lane; i < DIMM; i += 32) s += x[i]*g[i];
#pragma unroll
    for (int o = 16; o > 0; o >>= 1) s += __shfl_xor_sync(0xffffffffu, s, o);
    __shared__ float sc[NEXP];
    if (lane == 0) sc[w] = s;
    __syncthreads();
    if (threadIdx.x == 0) {
        float mx = sc[0];
        for (int e = 1; e < NEXP; e++) mx = fmaxf(mx, sc[e]);
        float p[NEXP]; float sum = 0.f;
        for (int e = 0; e < NEXP; e++) { p[e] = expf(sc[e]-mx); sum += p[e]; }
        for (int e = 0; e < NEXP; e++) p[e] /= sum;
        int i0 = 0;
        for (int e = 1; e < NEXP; e++) if (p[e] > p[i0]) i0 = e;
        int i1 = -1;
        for (int e = 0; e < NEXP; e++)
            if (e != i0 && (i1 < 0 || p[e] > p[i1])) i1 = e;
        tidx[n*2]   = i0; tidx[n*2+1] = i1;
        tw[n*2]     = p[i0]; tw[n*2+1] = p[i1];
        atomicAdd(&counts[i0], 1);
        atomicAdd(&counts[i1], 1);
    }
}

__global__ void prefix_kernel(const int* __restrict__ counts, int* __restrict__ offs,
                              int* __restrict__ fill) {
    if (threadIdx.x == 0) {
        int a = 0;
        for (int e = 0; e < NEXP; e++) { offs[e] = a; a += counts[e]; }
        offs[NEXP] = a;
    }
    if (threadIdx.x < NEXP) fill[threadIdx.x] = 0;
}

__global__ void scatter_kernel(const int* __restrict__ tidx,
                               const int* __restrict__ offs, int* __restrict__ fill,
                               int* __restrict__ tok, int* __restrict__ smap) {
    int n = blockIdx.x*blockDim.x + threadIdx.x;
    if (n >= NTOK) return;
#pragma unroll
    for (int j = 0; j < TOPK; j++) {
        int e = tidx[n*2+j];
        int slot = offs[e] + atomicAdd(&fill[e], 1);
        tok[slot] = n;
        smap[n*2+j] = slot;
    }
}

__global__ void silu_mul_hh(const __half* __restrict__ a, const __half* __restrict__ b,
                            __half* __restrict__ o, size_t n) {
    size_t i = ((size_t)blockIdx.x*blockDim.x + threadIdx.x)*8;
    if (i >= n) return;
    uint4 av = *(const uint4*)(a + i);
    uint4 bv = *(const uint4*)(b + i);
    uint4 ov;
    uint32_t* ap = (uint32_t*)&av;
    uint32_t* bp = (uint32_t*)&bv;
    uint32_t* op = (uint32_t*)&ov;
#pragma unroll
    for (int j = 0; j < 4; j++) {
        float2 af = __half22float2(*(__half2*)&ap[j]);
        float2 bf = __half22float2(*(__half2*)&bp[j]);
        float r0 = af.x / (1.f + __expf(-af.x)) * bf.x;
        float r1 = af.y / (1.f + __expf(-af.y)) * bf.y;
        op[j] = f2h2(r0, r1);
    }
    *(uint4*)(o + i) = ov;
}

// ================= launcher =================
extern "C" void kernel_launch(void* const* d_in, const int* in_sizes, int n_in,
                              void* d_out, int out_size) {
    (void)in_sizes; (void)n_in; (void)out_size;
    const float* x     = (const float*)d_in[0];
    const float* freqs = (const float*)d_in[1];
    const float* att_w = (const float*)d_in[2];
    const float* wq    = (const float*)d_in[3];
    const float* wk    = (const float*)d_in[4];
    const float* wv    = (const float*)d_in[5];
    const float* wo    = (const float*)d_in[6];
    const float* ffn_w = (const float*)d_in[7];
    const float* gw    = (const float*)d_in[8];
    const float* ew1   = (const float*)d_in[9];
    const float* ew2   = (const float*)d_in[10];
    const float* ew3   = (const float*)d_in[11];
    const float* sw1   = (const float*)d_in[12];
    const float* sw2   = (const float*)d_in[13];
    const float* sw3   = (const float*)d_in[14];
    float* out = (float*)d_out;

    __half *wqkvh,*woh,*e13h,*e2h,*s13wh,*s2wh,*xnh,*qkvh,*atth,*hnh;
    __half *h13h,*g13h,*s13hh,*s13h,*eoh;
    float *h,*hn32,*tw;
    int *tidx,*counts,*offs,*fill,*tok,*smap;
    cudaGetSymbolAddress((void**)&wqkvh, g_wqkvh);
    cudaGetSymbolAddress((void**)&woh,   g_woh);
    cudaGetSymbolAddress((void**)&e13h,  g_e13h);
    cudaGetSymbolAddress((void**)&e2h,   g_e2h);
    cudaGetSymbolAddress((void**)&s13wh, g_s13wh);
    cudaGetSymbolAddress((void**)&s2wh,  g_s2wh);
    cudaGetSymbolAddress((void**)&xnh,   g_xnh);
    cudaGetSymbolAddress((void**)&qkvh,  g_qkvh);
    cudaGetSymbolAddress((void**)&atth,  g_atth);
    cudaGetSymbolAddress((void**)&hnh,   g_hnh);
    cudaGetSymbolAddress((void**)&h13h,  g_h13h);
    cudaGetSymbolAddress((void**)&g13h,  g_g13h);
    cudaGetSymbolAddress((void**)&s13hh, g_s13hh);
    cudaGetSymbolAddress((void**)&s13h,  g_s13h);
    cudaGetSymbolAddress((void**)&eoh,   g_eoh);
    cudaGetSymbolAddress((void**)&h,     g_h);
    cudaGetSymbolAddress((void**)&hn32,  g_hn32);
    cudaGetSymbolAddress((void**)&tidx,  g_topk_idx);
    cudaGetSymbolAddress((void**)&tw,    g_topk_w);
    cudaGetSymbolAddress((void**)&counts, g_counts);
    cudaGetSymbolAddress((void**)&offs,   g_offsets);
    cudaGetSymbolAddress((void**)&fill,   g_fill);
    cudaGetSymbolAddress((void**)&tok,    g_tok_idx);
    cudaGetSymbolAddress((void**)&smap,   g_slot_map);

    cudaFuncSetAttribute(gemm2<false,false,false,true ,true ,false>, cudaFuncAttributeMaxDynamicSharedMemorySize, SMEMB);
    cudaFuncSetAttribute(gemm2<false,false,true, false,false,false>, cudaFuncAttributeMaxDynamicSharedMemorySize, SMEMB);
    cudaFuncSetAttribute(gemm2<true, true, false,true ,false,false>, cudaFuncAttributeMaxDynamicSharedMemorySize, SMEMB);
    cudaFuncSetAttribute(gemm2<false,true, false,true ,false,false>, cudaFuncAttributeMaxDynamicSharedMemorySize, SMEMB);
    cudaFuncSetAttribute(gemm2<false,false,false,true ,false,false>, cudaFuncAttributeMaxDynamicSharedMemorySize, SMEMB);
    cudaFuncSetAttribute(gemm2<false,false,true, false,false,true >, cudaFuncAttributeMaxDynamicSharedMemorySize, SMEMB);

    const int T = 256;
    const int WQN = DIMM*DIMM;
    const int EWN = DIMM*HIDD;

    // ---- fused weight conversion ----
    {
        CvtArgs a;
        a.s[0]=wq;  a.d[0]=wqkvh;         a.sb[0]=0;
        a.s[1]=wk;  a.d[1]=wqkvh+WQN;     a.sb[1]=512;
        a.s[2]=wv;  a.d[2]=wqkvh+2*WQN;   a.sb[2]=1024;
        a.s[3]=wo;  a.d[3]=woh;           a.sb[3]=1536;
        a.s[4]=ew1; a.d[4]=e13h;                        a.sb[4]=2048;
        a.s[5]=ew3; a.d[5]=e13h+(size_t)NEXP*EWN;       a.sb[5]=6144;
        a.s[6]=ew2; a.d[6]=e2h;                         a.sb[6]=10240;
        a.s[7]=sw1; a.d[7]=s13wh;         a.sb[7]=14336;
        a.s[8]=sw3; a.d[8]=s13wh+EWN;     a.sb[8]=14848;
        a.s[9]=sw2; a.d[9]=s2wh;          a.sb[9]=15360;
        cvt_all<<<15872, T>>>(a);
    }

    // 1) attention pre-norm
    rmsnorm_kernel<<<NTOK, T>>>(x, att_w, xnh, nullptr, nullptr);

    // 2) QKV with fused RoPE
    gemm2<false,false,false,true,true,false><<<dim3(32,8,3), T, SMEMB>>>(
        xnh, wqkvh, qkvh, nullptr, NTOK, 1.f,
        0, (long long)DIMM*DIMM, (long long)NTOK*DIMM, 0, nullptr, nullptr,
        freqs, nullptr, nullptr, nullptr);

    // 3) flash attention
    flash_attn<<<dim3(SLEN/128, BSZ*NHEAD), T>>>(qkvh, atth);

    // 4) h = x + att @ wo
    gemm2<false,false,true,false,false,false><<<dim3(32,8,1), T, SMEMB>>>(
        atth, woh, h, x, NTOK, 1.f, 0, 0, 0, 0, nullptr, nullptr,
        nullptr, nullptr, nullptr, nullptr);

    // 5) ffn pre-norm (also zeroes gate counts)
    rmsnorm_kernel<<<NTOK, T>>>(h, ffn_w, hnh, hn32, counts);

    // 6) gate + routing
    gate_topk<<<NTOK, T>>>(hn32, gw, tidx, tw, counts);
    prefix_kernel<<<1, 32>>>(counts, offs, fill);
    scatter_kernel<<<(NTOK + T - 1)/T, T>>>(tidx, offs, fill, tok, smap);

    // 7) experts
    gemm2<true,true,false,true,false,false><<<dim3(32,8,16), T, SMEMB>>>(
        hnh, e13h, h13h, nullptr, 0, 1.f,
        0, (long long)EWN, 0, (long long)NSLOT*HIDD, tok, offs,
        nullptr, nullptr, nullptr, nullptr);
    silu_mul_hh<<<(unsigned)(((size_t)NSLOT*HIDD)/2048), T>>>(
        h13h, h13h + (size_t)NSLOT*HIDD, g13h, (size_t)NSLOT*HIDD);
    gemm2<false,true,false,true,false,false><<<dim3(32,8,NEXP), T, SMEMB>>>(
        g13h, e2h, eoh, nullptr, 0, 1.f,
        0, (long long)EWN, 0, 0, nullptr, offs,
        nullptr, nullptr, nullptr, nullptr);

    // 8) shared expert
    gemm2<false,false,false,true,false,false><<<dim3(32,8,2), T, SMEMB>>>(
        hnh, s13wh, s13hh, nullptr, NTOK, 1.f,
        0, (long long)EWN, (long long)NTOK*HIDD, 0, nullptr, nullptr,
        nullptr, nullptr, nullptr, nullptr);
    silu_mul_hh<<<(unsigned)(((size_t)NTOK*HIDD)/2048), T>>>(
        s13hh, s13hh + (size_t)NTOK*HIDD, s13h, (size_t)NTOK*HIDD);

    // 9) final: out = h + s13 @ sw2 + routed combine (fused)
    gemm2<false,false,true,false,false,true><<<dim3(32,8,1), T, SMEMB>>>(
        s13h, s2wh, out, h, NTOK, 1.f, 0, 0, 0, 0, nullptr, nullptr,
        nullptr, eoh, smap, tw);
}